// round 13
// baseline (speedup 1.0000x reference)
#include <cuda_runtime.h>
#include <cuda_bf16.h>
#include <cstdint>

#define D 128
#define MAXN 50176        // padded node capacity (actual N = 50000)
#define MAXE 600000
#define SCAN_BLK 512
#define NSCAN (MAXN / SCAN_BLK)   // 98
#define WELEMS (128 * 384)

// ---------------- scratch (no allocs allowed) ----------------
__device__ int      g_cnt[MAXN];       // zeroed in scan1 (self-restoring)
__device__ int      g_fill[MAXN];      // set by scan3 to row start each call
__device__ int      g_row[MAXN + 1];
__device__ int      g_bsum[NSCAN];
__device__ int      g_csrc[MAXE];
__device__ float    g_inv[MAXN];
__device__ uint32_t g_xpk[MAXN * D];   // packed (bf16 hi | bf16 lo) of x
__device__ uint32_t g_h1pk[MAXN * D];  // packed hop1
__device__ uint32_t g_h2pk[MAXN * D];  // packed hop2
__device__ uint32_t g_wpk[WELEMS];     // packed W

// ---------------- packed split helpers ----------------
__device__ __forceinline__ uint32_t packsplit(float f) {
    uint32_t h = (uint32_t)__bfloat16_as_ushort(__float2bfloat16(f)) << 16;
    float lo = f - __uint_as_float(h);
    return h | (uint32_t)__bfloat16_as_ushort(__float2bfloat16(lo));
}
__device__ __forceinline__ float recon(uint32_t u) {
    return __uint_as_float(u & 0xFFFF0000u) + __uint_as_float(u << 16);
}
__device__ __forceinline__ uint32_t prmt(uint32_t a, uint32_t b, uint32_t sel) {
    uint32_t r;
    asm("prmt.b32 %0, %1, %2, %3;" : "=r"(r) : "r"(a), "r"(b), "r"(sel));
    return r;
}

// ---------------- convert x and W to packed planes ----------------
__global__ void convert_kernel(const float* __restrict__ x,
                               const float* __restrict__ W, int nx) {
    int i = blockIdx.x * blockDim.x + threadIdx.x;
    if (i < nx) g_xpk[i] = packsplit(x[i]);
    int j = i - nx;
    if (j >= 0 && j < WELEMS) g_wpk[j] = packsplit(W[j]);
}

// ---------------- in-degree histogram (2 edges/thread) ----------------
__global__ void degree_kernel(const int* __restrict__ ei, int E) {
    int i = blockIdx.x * blockDim.x + threadIdx.x;
    int h = E >> 1;
    if (i < h) {
        int2 d2 = ((const int2*)(ei + E))[i];
        atomicAdd(&g_cnt[d2.x], 1);
        atomicAdd(&g_cnt[d2.y], 1);
    }
    if (i == 0 && (E & 1)) atomicAdd(&g_cnt[ei[E + E - 1]], 1);
}

// ---------------- scan1: per-block exclusive prefix, block sum, inv-degree ----------------
__global__ void scan1_kernel() {
    __shared__ int sh[SCAN_BLK];
    int t = threadIdx.x;
    int i = blockIdx.x * SCAN_BLK + t;
    int v = g_cnt[i];
    g_cnt[i] = 0;                              // self-restore for next replay
    sh[t] = v;
    __syncthreads();
#pragma unroll
    for (int off = 1; off < SCAN_BLK; off <<= 1) {
        int u = (t >= off) ? sh[t - off] : 0;
        __syncthreads();
        sh[t] += u;
        __syncthreads();
    }
    g_row[i] = sh[t] - v;                      // exclusive within block
    g_inv[i] = 1.0f / fmaxf((float)v, 1.0f);
    if (t == SCAN_BLK - 1) g_bsum[blockIdx.x] = sh[t];
}

// ---------------- scan3: add block offsets (redundant per-block scan of bsum) ----------------
__global__ void scan3_kernel() {
    __shared__ int sh[128];
    int t = threadIdx.x;
    if (t < 128) sh[t] = (t < NSCAN) ? g_bsum[t] : 0;
    __syncthreads();
#pragma unroll
    for (int off = 1; off < 128; off <<= 1) {
        int u = (t < 128 && t >= off) ? sh[t - off] : 0;
        __syncthreads();
        if (t < 128) sh[t] += u;
        __syncthreads();
    }
    int offset = (blockIdx.x == 0) ? 0 : sh[blockIdx.x - 1];
    int i = blockIdx.x * SCAN_BLK + t;
    int r = g_row[i] + offset;
    g_row[i] = r;
    g_fill[i] = r;
}

// ---------------- CSR fill (4 edges/thread) ----------------
__global__ void fill_kernel(const int* __restrict__ ei, int E) {
    int i = blockIdx.x * blockDim.x + threadIdx.x;
    int q = E >> 2;
    if (i < q) {
        int4 s4 = ((const int4*)ei)[i];
        int4 d4 = ((const int4*)(ei + E))[i];
        g_csrc[atomicAdd(&g_fill[d4.x], 1)] = s4.x;
        g_csrc[atomicAdd(&g_fill[d4.y], 1)] = s4.y;
        g_csrc[atomicAdd(&g_fill[d4.z], 1)] = s4.z;
        g_csrc[atomicAdd(&g_fill[d4.w], 1)] = s4.w;
    }
    if (i < (E & 3)) {
        int e = (q << 2) + i;
        g_csrc[atomicAdd(&g_fill[ei[E + e]], 1)] = ei[e];
    }
}

// ---------------- mean aggregation (pull): one warp per dst node ----------------
// pass 0: gather fp32 x -> g_h1pk.  pass 1: gather packed g_h1pk -> g_h2pk.
__global__ void hop_kernel(const float* __restrict__ x, int pass, int n) {
    int w = (blockIdx.x * blockDim.x + threadIdx.x) >> 5;
    if (w >= n) return;
    int lane = threadIdx.x & 31;

    int beg = g_row[w];
    int end = g_row[w + 1];

    float ax = 0.f, ay = 0.f, az = 0.f, aw = 0.f;

    if (pass == 0) {
        const float4* in = (const float4*)x;
        int j = beg;
        for (; j + 4 <= end; j += 4) {
            int s0 = __ldg(&g_csrc[j + 0]);
            int s1 = __ldg(&g_csrc[j + 1]);
            int s2 = __ldg(&g_csrc[j + 2]);
            int s3 = __ldg(&g_csrc[j + 3]);
            float4 v0 = __ldg(in + (size_t)s0 * 32 + lane);
            float4 v1 = __ldg(in + (size_t)s1 * 32 + lane);
            float4 v2 = __ldg(in + (size_t)s2 * 32 + lane);
            float4 v3 = __ldg(in + (size_t)s3 * 32 + lane);
            ax += v0.x; ay += v0.y; az += v0.z; aw += v0.w;
            ax += v1.x; ay += v1.y; az += v1.z; aw += v1.w;
            ax += v2.x; ay += v2.y; az += v2.z; aw += v2.w;
            ax += v3.x; ay += v3.y; az += v3.z; aw += v3.w;
        }
        for (; j < end; j++) {
            int s0 = __ldg(&g_csrc[j]);
            float4 v0 = __ldg(in + (size_t)s0 * 32 + lane);
            ax += v0.x; ay += v0.y; az += v0.z; aw += v0.w;
        }
    } else {
        const uint4* in = (const uint4*)g_h1pk;
        int j = beg;
        for (; j + 2 <= end; j += 2) {
            int s0 = __ldg(&g_csrc[j + 0]);
            int s1 = __ldg(&g_csrc[j + 1]);
            uint4 v0 = __ldg(in + (size_t)s0 * 32 + lane);
            uint4 v1 = __ldg(in + (size_t)s1 * 32 + lane);
            ax += recon(v0.x); ay += recon(v0.y); az += recon(v0.z); aw += recon(v0.w);
            ax += recon(v1.x); ay += recon(v1.y); az += recon(v1.z); aw += recon(v1.w);
        }
        for (; j < end; j++) {
            int s0 = __ldg(&g_csrc[j]);
            uint4 v0 = __ldg(in + (size_t)s0 * 32 + lane);
            ax += recon(v0.x); ay += recon(v0.y); az += recon(v0.z); aw += recon(v0.w);
        }
    }

    float inv = g_inv[w];
    uint32_t* op = (pass == 0) ? g_h1pk : g_h2pk;
    uint4 r;
    r.x = packsplit(ax * inv);
    r.y = packsplit(ay * inv);
    r.z = packsplit(az * inv);
    r.w = packsplit(aw * inv);
    *((uint4*)op + (size_t)w * 32 + lane) = r;
}

// ---------------- HMMA MMA helper ----------------
__device__ __forceinline__ void mma_bf16(float* c, const uint32_t* a, const uint32_t* b) {
    asm volatile(
        "mma.sync.aligned.m16n8k16.row.col.f32.bf16.bf16.f32 "
        "{%0,%1,%2,%3}, {%4,%5,%6,%7}, {%8,%9}, {%0,%1,%2,%3};"
        : "+f"(c[0]), "+f"(c[1]), "+f"(c[2]), "+f"(c[3])
        : "r"(a[0]), "r"(a[1]), "r"(a[2]), "r"(a[3]), "r"(b[0]), "r"(b[1]));
}

// ---------------- HMMA split-bf16 fused concat-GEMM (pre-packed operands) ----------------
// out = [x|hop1|hop2] @ W^T + b.  CTA: 128 nodes x 128 outs. 8 warps, warp 32x64.
// 3 passes per k-step: Ahi*Bhi + Alo*Bhi + Ahi*Blo (lo*lo dropped, ~2^-18).
#define SSTR 40   // padded bf16 row stride (conflict-free fragment LDS)
__global__ __launch_bounds__(256, 2)
void hmma_gemm_kernel(const float* __restrict__ bias,  // [128]
                      float* __restrict__ out, int n) {
    __shared__ __nv_bfloat16 Ahi[128][SSTR], Alo[128][SSTR];
    __shared__ __nv_bfloat16 Bhi[128][SSTR], Blo[128][SSTR];

    int tid = threadIdx.x;
    int wid = tid >> 5, lane = tid & 31;
    int wm = wid & 3;            // warp row:   m in [wm*32, +32)
    int wn = wid >> 2;           // warp col:   o in [wn*64, +64)
    int g = lane >> 2, tig = lane & 3;
    int m0 = blockIdx.x * 128;

    float acc[2][8][4];
#pragma unroll
    for (int mt = 0; mt < 2; mt++)
#pragma unroll
        for (int nt = 0; nt < 8; nt++)
#pragma unroll
            for (int q = 0; q < 4; q++) acc[mt][nt][q] = 0.f;

    int lrow = tid >> 1;                 // loader row 0..127
    int lh   = (tid & 1) * 16;           // k half within 32-chunk
    bool avalid = (m0 + lrow) < n;

#pragma unroll 1
    for (int kt = 0; kt < 12; kt++) {
        const uint32_t* A = (kt < 4) ? g_xpk : (kt < 8) ? g_h1pk : g_h2pk;
        int ka = (kt & 3) * 32;

        uint4 ap[4], wp[4];
        const uint4* app = (const uint4*)(A + (size_t)(m0 + lrow) * 128 + ka + lh);
        const uint4* wpp = (const uint4*)(g_wpk + (size_t)lrow * 384 + kt * 32 + lh);
#pragma unroll
        for (int q = 0; q < 4; q++) {
            ap[q] = avalid ? __ldg(app + q) : make_uint4(0u, 0u, 0u, 0u);
            wp[q] = __ldg(wpp + q);
        }

        __syncthreads();   // previous tile fully consumed
#pragma unroll
        for (int q = 0; q < 4; q++) {
            int kc = lh + q * 4;
            *(uint32_t*)&Ahi[lrow][kc]     = prmt(ap[q].x, ap[q].y, 0x7632);
            *(uint32_t*)&Ahi[lrow][kc + 2] = prmt(ap[q].z, ap[q].w, 0x7632);
            *(uint32_t*)&Alo[lrow][kc]     = prmt(ap[q].x, ap[q].y, 0x5410);
            *(uint32_t*)&Alo[lrow][kc + 2] = prmt(ap[q].z, ap[q].w, 0x5410);
            *(uint32_t*)&Bhi[lrow][kc]     = prmt(wp[q].x, wp[q].y, 0x7632);
            *(uint32_t*)&Bhi[lrow][kc + 2] = prmt(wp[q].z, wp[q].w, 0x7632);
            *(uint32_t*)&Blo[lrow][kc]     = prmt(wp[q].x, wp[q].y, 0x5410);
            *(uint32_t*)&Blo[lrow][kc + 2] = prmt(wp[q].z, wp[q].w, 0x5410);
        }
        __syncthreads();

#pragma unroll
        for (int ks = 0; ks < 2; ks++) {
            int kb = ks * 16 + tig * 2;

            uint32_t afh[2][4], afl[4];
#pragma unroll
            for (int mt = 0; mt < 2; mt++) {
                int am = wm * 32 + mt * 16 + g;
                afh[mt][0] = *(const uint32_t*)&Ahi[am][kb];
                afh[mt][1] = *(const uint32_t*)&Ahi[am + 8][kb];
                afh[mt][2] = *(const uint32_t*)&Ahi[am][kb + 8];
                afh[mt][3] = *(const uint32_t*)&Ahi[am + 8][kb + 8];
            }

            uint32_t bf[8][2];
#pragma unroll
            for (int nt = 0; nt < 8; nt++) {
                int nn = wn * 64 + nt * 8 + g;
                bf[nt][0] = *(const uint32_t*)&Bhi[nn][kb];
                bf[nt][1] = *(const uint32_t*)&Bhi[nn][kb + 8];
            }
#pragma unroll
            for (int mt = 0; mt < 2; mt++) {
                int am = wm * 32 + mt * 16 + g;
                afl[0] = *(const uint32_t*)&Alo[am][kb];
                afl[1] = *(const uint32_t*)&Alo[am + 8][kb];
                afl[2] = *(const uint32_t*)&Alo[am][kb + 8];
                afl[3] = *(const uint32_t*)&Alo[am + 8][kb + 8];
#pragma unroll
                for (int nt = 0; nt < 8; nt++) {
                    mma_bf16(acc[mt][nt], afh[mt], bf[nt]);
                    mma_bf16(acc[mt][nt], afl, bf[nt]);
                }
            }
#pragma unroll
            for (int nt = 0; nt < 8; nt++) {
                int nn = wn * 64 + nt * 8 + g;
                bf[nt][0] = *(const uint32_t*)&Blo[nn][kb];
                bf[nt][1] = *(const uint32_t*)&Blo[nn][kb + 8];
            }
#pragma unroll
            for (int mt = 0; mt < 2; mt++)
#pragma unroll
                for (int nt = 0; nt < 8; nt++)
                    mma_bf16(acc[mt][nt], afh[mt], bf[nt]);
        }
    }

    // epilogue: acc -> out (+bias)
#pragma unroll
    for (int mt = 0; mt < 2; mt++) {
        int row = m0 + wm * 32 + mt * 16 + g;
#pragma unroll
        for (int nt = 0; nt < 8; nt++) {
            int col = wn * 64 + nt * 8 + tig * 2;
            float2 bb = *(const float2*)&bias[col];
            if (row < n) {
                float2 r0 = make_float2(acc[mt][nt][0] + bb.x, acc[mt][nt][1] + bb.y);
                *(float2*)&out[(size_t)row * 128 + col] = r0;
            }
            if (row + 8 < n) {
                float2 r1 = make_float2(acc[mt][nt][2] + bb.x, acc[mt][nt][3] + bb.y);
                *(float2*)&out[(size_t)(row + 8) * 128 + col] = r1;
            }
        }
    }
}

// ---------------- launch ----------------
extern "C" void kernel_launch(void* const* d_in, const int* in_sizes, int n_in,
                              void* d_out, int out_size) {
    const float* x    = (const float*)d_in[0];
    const int*   ei   = (const int*)d_in[1];      // int32 (JAX x64 disabled)
    const float* W    = (const float*)d_in[2];
    const float* bias = (const float*)d_in[3];
    float*       out  = (float*)d_out;

    int n = in_sizes[0] / D;      // 50000
    int E = in_sizes[1] / 2;      // 600000

    // pre-split x and W into packed bf16 (hi|lo) planes
    int nx = n * D;
    convert_kernel<<<(nx + WELEMS + 255) / 256, 256>>>(x, W, nx);

    // CSR build (by destination)
    degree_kernel<<<(E / 2 + 255) / 256, 256>>>(ei, E);
    scan1_kernel<<<NSCAN, SCAN_BLK>>>();
    scan3_kernel<<<NSCAN, SCAN_BLK>>>();
    fill_kernel<<<(E / 4 + 255) / 256, 256>>>(ei, E);

    // two mean-propagation hops (packed outputs)
    int hop_blocks = (n * 32 + 255) / 256;
    hop_kernel<<<hop_blocks, 256>>>(x, 0, n);
    hop_kernel<<<hop_blocks, 256>>>(x, 1, n);

    // split-bf16 HMMA GEMM on pre-packed operands
    hmma_gemm_kernel<<<(n + 127) / 128, 256>>>(bias, out, n);
}

// round 14
// speedup vs baseline: 1.0554x; 1.0554x over previous
#include <cuda_runtime.h>
#include <cuda_bf16.h>
#include <cuda_fp16.h>
#include <cstdint>

#define D 128
#define MAXN 50176        // padded node capacity (actual N = 50000)
#define MAXE 600000
#define SCAN_BLK 512
#define NSCAN (MAXN / SCAN_BLK)   // 98

// ---------------- scratch (no allocs allowed) ----------------
__device__ int    g_cnt[MAXN];         // zeroed in scan1 (self-restoring)
__device__ int    g_fill[MAXN];        // set by scan3 to row start each call
__device__ int    g_row[MAXN + 1];
__device__ int    g_bsum[NSCAN];
__device__ int    g_csrc[MAXE];
__device__ float  g_inv[MAXN];
__device__ float  g_hop1[MAXN * D];    // fp32 (GEMM input)
__device__ float  g_hop2[MAXN * D];    // fp32 (GEMM input)
__device__ __half g_xh[MAXN * D];      // fp16 x   (hop1 gather input)
__device__ __half g_h1h[MAXN * D];     // fp16 hop1 (hop2 gather input)

// ---------------- x -> fp16 convert ----------------
__global__ void convert_kernel(const float* __restrict__ x, int nx4) {
    int i = blockIdx.x * blockDim.x + threadIdx.x;
    if (i < nx4) {
        float4 v = ((const float4*)x)[i];
        __half2 h0 = __floats2half2_rn(v.x, v.y);
        __half2 h1 = __floats2half2_rn(v.z, v.w);
        uint2 u;
        u.x = *(uint32_t*)&h0;
        u.y = *(uint32_t*)&h1;
        ((uint2*)g_xh)[i] = u;
    }
}

// ---------------- in-degree histogram (2 edges/thread) ----------------
__global__ void degree_kernel(const int* __restrict__ ei, int E) {
    int i = blockIdx.x * blockDim.x + threadIdx.x;
    if (i < E / 2) {
        int2 d2 = ((const int2*)(ei + E))[i];
        atomicAdd(&g_cnt[d2.x], 1);
        atomicAdd(&g_cnt[d2.y], 1);
    }
}

// ---------------- scan1: per-block exclusive prefix, block sum, inv-degree ----------------
__global__ void scan1_kernel() {
    __shared__ int sh[SCAN_BLK];
    int t = threadIdx.x;
    int i = blockIdx.x * SCAN_BLK + t;
    int v = g_cnt[i];
    g_cnt[i] = 0;                              // self-restore for next replay
    sh[t] = v;
    __syncthreads();
#pragma unroll
    for (int off = 1; off < SCAN_BLK; off <<= 1) {
        int u = (t >= off) ? sh[t - off] : 0;
        __syncthreads();
        sh[t] += u;
        __syncthreads();
    }
    g_row[i] = sh[t] - v;                      // exclusive within block
    g_inv[i] = 1.0f / fmaxf((float)v, 1.0f);
    if (t == SCAN_BLK - 1) g_bsum[blockIdx.x] = sh[t];
}

// ---------------- scan3: add block offsets (redundant per-block scan of bsum) ----------------
__global__ void scan3_kernel() {
    __shared__ int sh[128];
    int t = threadIdx.x;
    if (t < 128) sh[t] = (t < NSCAN) ? g_bsum[t] : 0;
    __syncthreads();
#pragma unroll
    for (int off = 1; off < 128; off <<= 1) {
        int u = (t < 128 && t >= off) ? sh[t - off] : 0;
        __syncthreads();
        if (t < 128) sh[t] += u;
        __syncthreads();
    }
    int offset = (blockIdx.x == 0) ? 0 : sh[blockIdx.x - 1];
    int i = blockIdx.x * SCAN_BLK + t;
    int r = g_row[i] + offset;
    g_row[i] = r;
    g_fill[i] = r;
}

// ---------------- CSR fill ----------------
__global__ void fill_kernel(const int* __restrict__ ei, int E) {
    int i = blockIdx.x * blockDim.x + threadIdx.x;
    if (i < E / 2) {
        int2 s2 = ((const int2*)ei)[i];
        int2 d2 = ((const int2*)(ei + E))[i];
        int p0 = atomicAdd(&g_fill[d2.x], 1);
        g_csrc[p0] = s2.x;
        int p1 = atomicAdd(&g_fill[d2.y], 1);
        g_csrc[p1] = s2.y;
    }
}

// ---------------- mean aggregation (pull, fp16 gather): one warp per dst node ----------------
// pass 0: gather g_xh  -> g_hop1 (fp32) + g_h1h (fp16)
// pass 1: gather g_h1h -> g_hop2 (fp32)
__global__ void hop_kernel(int pass, int n) {
    int w = (blockIdx.x * blockDim.x + threadIdx.x) >> 5;
    if (w >= n) return;
    int lane = threadIdx.x & 31;

    const uint2* in = (const uint2*)((pass == 0) ? g_xh : g_h1h);

    int beg = g_row[w];
    int end = g_row[w + 1];

    float ax = 0.f, ay = 0.f, az = 0.f, aw = 0.f;
    int j = beg;
    for (; j + 4 <= end; j += 4) {
        int s0 = __ldg(&g_csrc[j + 0]);
        int s1 = __ldg(&g_csrc[j + 1]);
        int s2 = __ldg(&g_csrc[j + 2]);
        int s3 = __ldg(&g_csrc[j + 3]);
        uint2 v0 = __ldg(in + (size_t)s0 * 32 + lane);
        uint2 v1 = __ldg(in + (size_t)s1 * 32 + lane);
        uint2 v2 = __ldg(in + (size_t)s2 * 32 + lane);
        uint2 v3 = __ldg(in + (size_t)s3 * 32 + lane);
        float2 f;
        f = __half22float2(*(__half2*)&v0.x); ax += f.x; ay += f.y;
        f = __half22float2(*(__half2*)&v0.y); az += f.x; aw += f.y;
        f = __half22float2(*(__half2*)&v1.x); ax += f.x; ay += f.y;
        f = __half22float2(*(__half2*)&v1.y); az += f.x; aw += f.y;
        f = __half22float2(*(__half2*)&v2.x); ax += f.x; ay += f.y;
        f = __half22float2(*(__half2*)&v2.y); az += f.x; aw += f.y;
        f = __half22float2(*(__half2*)&v3.x); ax += f.x; ay += f.y;
        f = __half22float2(*(__half2*)&v3.y); az += f.x; aw += f.y;
    }
    for (; j < end; j++) {
        int s0 = __ldg(&g_csrc[j]);
        uint2 v0 = __ldg(in + (size_t)s0 * 32 + lane);
        float2 f;
        f = __half22float2(*(__half2*)&v0.x); ax += f.x; ay += f.y;
        f = __half22float2(*(__half2*)&v0.y); az += f.x; aw += f.y;
    }

    float inv = g_inv[w];
    ax *= inv; ay *= inv; az *= inv; aw *= inv;

    if (pass == 0) {
        ((float4*)g_hop1)[(size_t)w * 32 + lane] = make_float4(ax, ay, az, aw);
        __half2 h0 = __floats2half2_rn(ax, ay);
        __half2 h1 = __floats2half2_rn(az, aw);
        uint2 u;
        u.x = *(uint32_t*)&h0;
        u.y = *(uint32_t*)&h1;
        ((uint2*)g_h1h)[(size_t)w * 32 + lane] = u;
    } else {
        ((float4*)g_hop2)[(size_t)w * 32 + lane] = make_float4(ax, ay, az, aw);
    }
}

// ---------------- bf16 split helpers ----------------
__device__ __forceinline__ void split2(float f0, float f1, uint32_t& hi, uint32_t& lo) {
    __nv_bfloat16 h0 = __float2bfloat16(f0);
    __nv_bfloat16 h1 = __float2bfloat16(f1);
    __nv_bfloat16 l0 = __float2bfloat16(f0 - __bfloat162float(h0));
    __nv_bfloat16 l1 = __float2bfloat16(f1 - __bfloat162float(h1));
    hi = (uint32_t)__bfloat16_as_ushort(h0) | ((uint32_t)__bfloat16_as_ushort(h1) << 16);
    lo = (uint32_t)__bfloat16_as_ushort(l0) | ((uint32_t)__bfloat16_as_ushort(l1) << 16);
}

__device__ __forceinline__ void mma_bf16(float* c, const uint32_t* a, const uint32_t* b) {
    asm volatile(
        "mma.sync.aligned.m16n8k16.row.col.f32.bf16.bf16.f32 "
        "{%0,%1,%2,%3}, {%4,%5,%6,%7}, {%8,%9}, {%0,%1,%2,%3};"
        : "+f"(c[0]), "+f"(c[1]), "+f"(c[2]), "+f"(c[3])
        : "r"(a[0]), "r"(a[1]), "r"(a[2]), "r"(a[3]), "r"(b[0]), "r"(b[1]));
}

// ---------------- HMMA split-bf16 fused concat-GEMM (proven R9/R12) ----------------
#define SSTR 40   // padded bf16 row stride (conflict-free fragment LDS)
__global__ __launch_bounds__(256, 2)
void hmma_gemm_kernel(const float* __restrict__ x,
                      const float* __restrict__ W,     // [128, 384]
                      const float* __restrict__ bias,  // [128]
                      float* __restrict__ out, int n) {
    __shared__ __nv_bfloat16 Ahi[128][SSTR], Alo[128][SSTR];
    __shared__ __nv_bfloat16 Bhi[128][SSTR], Blo[128][SSTR];

    int tid = threadIdx.x;
    int wid = tid >> 5, lane = tid & 31;
    int wm = wid & 3;            // warp row:   m in [wm*32, +32)
    int wn = wid >> 2;           // warp col:   o in [wn*64, +64)
    int g = lane >> 2, tig = lane & 3;
    int m0 = blockIdx.x * 128;

    float acc[2][8][4];
#pragma unroll
    for (int mt = 0; mt < 2; mt++)
#pragma unroll
        for (int nt = 0; nt < 8; nt++)
#pragma unroll
            for (int q = 0; q < 4; q++) acc[mt][nt][q] = 0.f;

    int lrow = tid >> 1;                 // loader row 0..127
    int lh   = (tid & 1) * 16;           // k half within 32-chunk
    bool avalid = (m0 + lrow) < n;

#pragma unroll 1
    for (int kt = 0; kt < 12; kt++) {
        const float* A = (kt < 4) ? x : (kt < 8) ? g_hop1 : g_hop2;
        int ka = (kt & 3) * 32;

        float4 av[4], wv[4];
        const float4* ap = (const float4*)(A + (size_t)(m0 + lrow) * 128 + ka + lh);
        const float4* wp = (const float4*)(W + (size_t)lrow * 384 + kt * 32 + lh);
#pragma unroll
        for (int q = 0; q < 4; q++) {
            av[q] = avalid ? __ldg(ap + q) : make_float4(0.f, 0.f, 0.f, 0.f);
            wv[q] = __ldg(wp + q);
        }

        __syncthreads();   // previous tile fully consumed
#pragma unroll
        for (int q = 0; q < 4; q++) {
            uint32_t h0, l0, h1, l1;
            int kc = lh + q * 4;
            split2(av[q].x, av[q].y, h0, l0);
            split2(av[q].z, av[q].w, h1, l1);
            *(uint32_t*)&Ahi[lrow][kc]     = h0;
            *(uint32_t*)&Ahi[lrow][kc + 2] = h1;
            *(uint32_t*)&Alo[lrow][kc]     = l0;
            *(uint32_t*)&Alo[lrow][kc + 2] = l1;
            split2(wv[q].x, wv[q].y, h0, l0);
            split2(wv[q].z, wv[q].w, h1, l1);
            *(uint32_t*)&Bhi[lrow][kc]     = h0;
            *(uint32_t*)&Bhi[lrow][kc + 2] = h1;
            *(uint32_t*)&Blo[lrow][kc]     = l0;
            *(uint32_t*)&Blo[lrow][kc + 2] = l1;
        }
        __syncthreads();

#pragma unroll
        for (int ks = 0; ks < 2; ks++) {
            int kb = ks * 16 + tig * 2;

            uint32_t afh[2][4], afl[4];
#pragma unroll
            for (int mt = 0; mt < 2; mt++) {
                int am = wm * 32 + mt * 16 + g;
                afh[mt][0] = *(const uint32_t*)&Ahi[am][kb];
                afh[mt][1] = *(const uint32_t*)&Ahi[am + 8][kb];
                afh[mt][2] = *(const uint32_t*)&Ahi[am][kb + 8];
                afh[mt][3] = *(const uint32_t*)&Ahi[am + 8][kb + 8];
            }

            uint32_t bf[8][2];
#pragma unroll
            for (int nt = 0; nt < 8; nt++) {
                int nn = wn * 64 + nt * 8 + g;
                bf[nt][0] = *(const uint32_t*)&Bhi[nn][kb];
                bf[nt][1] = *(const uint32_t*)&Bhi[nn][kb + 8];
            }
#pragma unroll
            for (int mt = 0; mt < 2; mt++) {
                int am = wm * 32 + mt * 16 + g;
                afl[0] = *(const uint32_t*)&Alo[am][kb];
                afl[1] = *(const uint32_t*)&Alo[am + 8][kb];
                afl[2] = *(const uint32_t*)&Alo[am][kb + 8];
                afl[3] = *(const uint32_t*)&Alo[am + 8][kb + 8];
#pragma unroll
                for (int nt = 0; nt < 8; nt++) {
                    mma_bf16(acc[mt][nt], afh[mt], bf[nt]);
                    mma_bf16(acc[mt][nt], afl, bf[nt]);
                }
            }
#pragma unroll
            for (int nt = 0; nt < 8; nt++) {
                int nn = wn * 64 + nt * 8 + g;
                bf[nt][0] = *(const uint32_t*)&Blo[nn][kb];
                bf[nt][1] = *(const uint32_t*)&Blo[nn][kb + 8];
            }
#pragma unroll
            for (int mt = 0; mt < 2; mt++)
#pragma unroll
                for (int nt = 0; nt < 8; nt++)
                    mma_bf16(acc[mt][nt], afh[mt], bf[nt]);
        }
    }

    // epilogue: acc -> out (+bias)
#pragma unroll
    for (int mt = 0; mt < 2; mt++) {
        int row = m0 + wm * 32 + mt * 16 + g;
#pragma unroll
        for (int nt = 0; nt < 8; nt++) {
            int col = wn * 64 + nt * 8 + tig * 2;
            float2 bb = *(const float2*)&bias[col];
            if (row < n) {
                float2 r0 = make_float2(acc[mt][nt][0] + bb.x, acc[mt][nt][1] + bb.y);
                *(float2*)&out[(size_t)row * 128 + col] = r0;
            }
            if (row + 8 < n) {
                float2 r1 = make_float2(acc[mt][nt][2] + bb.x, acc[mt][nt][3] + bb.y);
                *(float2*)&out[(size_t)(row + 8) * 128 + col] = r1;
            }
        }
    }
}

// ---------------- launch ----------------
extern "C" void kernel_launch(void* const* d_in, const int* in_sizes, int n_in,
                              void* d_out, int out_size) {
    const float* x    = (const float*)d_in[0];
    const int*   ei   = (const int*)d_in[1];      // int32 (JAX x64 disabled)
    const float* W    = (const float*)d_in[2];
    const float* bias = (const float*)d_in[3];
    float*       out  = (float*)d_out;

    int n = in_sizes[0] / D;      // 50000
    int E = in_sizes[1] / 2;      // 600000

    // x -> fp16 (hop gather input)
    int nx4 = n * D / 4;
    convert_kernel<<<(nx4 + 255) / 256, 256>>>(x, nx4);

    // CSR build (by destination)
    degree_kernel<<<(E / 2 + 255) / 256, 256>>>(ei, E);
    scan1_kernel<<<NSCAN, SCAN_BLK>>>();
    scan3_kernel<<<NSCAN, SCAN_BLK>>>();
    fill_kernel<<<(E / 2 + 255) / 256, 256>>>(ei, E);

    // two mean-propagation hops (fp16 gathers, fp32 accumulate/output)
    int hop_blocks = (n * 32 + 255) / 256;
    hop_kernel<<<hop_blocks, 256>>>(0, n);
    hop_kernel<<<hop_blocks, 256>>>(1, n);

    // split-bf16 HMMA GEMM (fp32 inputs, unchanged)
    hmma_gemm_kernel<<<(n + 127) / 128, 256>>>(x, W, bias, out, n);
}

// round 15
// speedup vs baseline: 1.2834x; 1.2160x over previous
#include <cuda_runtime.h>
#include <cuda_fp16.h>
#include <cstdint>

#define D 128
#define MAXN 50176        // padded node capacity (actual N = 50000)
#define MAXE 600000
#define SCAN_BLK 512
#define NSCAN (MAXN / SCAN_BLK)   // 98

// ---------------- scratch (no allocs allowed) ----------------
__device__ int   g_cnt[MAXN];          // zeroed in scan1 (self-restoring)
__device__ int   g_fill[MAXN];         // set by scan3 to row start each call
__device__ int   g_row[MAXN + 1];
__device__ int   g_bsum[NSCAN];
__device__ int   g_csrc[MAXE];
__device__ float g_inv[MAXN];
__device__ float g_hop1[MAXN * D];
__device__ float g_hop2[MAXN * D];

// ---------------- in-degree histogram (2 edges/thread) ----------------
__global__ void degree_kernel(const int* __restrict__ ei, int E) {
    int i = blockIdx.x * blockDim.x + threadIdx.x;
    if (i < E / 2) {
        int2 d2 = ((const int2*)(ei + E))[i];
        atomicAdd(&g_cnt[d2.x], 1);
        atomicAdd(&g_cnt[d2.y], 1);
    }
}

// ---------------- scan1: per-block exclusive prefix, block sum, inv-degree ----------------
__global__ void scan1_kernel() {
    __shared__ int sh[SCAN_BLK];
    int t = threadIdx.x;
    int i = blockIdx.x * SCAN_BLK + t;
    int v = g_cnt[i];
    g_cnt[i] = 0;                              // self-restore for next replay
    sh[t] = v;
    __syncthreads();
#pragma unroll
    for (int off = 1; off < SCAN_BLK; off <<= 1) {
        int u = (t >= off) ? sh[t - off] : 0;
        __syncthreads();
        sh[t] += u;
        __syncthreads();
    }
    g_row[i] = sh[t] - v;                      // exclusive within block
    g_inv[i] = 1.0f / fmaxf((float)v, 1.0f);
    if (t == SCAN_BLK - 1) g_bsum[blockIdx.x] = sh[t];
}

// ---------------- scan3: add block offsets (redundant per-block scan of bsum) ----------------
__global__ void scan3_kernel() {
    __shared__ int sh[128];
    int t = threadIdx.x;
    if (t < 128) sh[t] = (t < NSCAN) ? g_bsum[t] : 0;
    __syncthreads();
#pragma unroll
    for (int off = 1; off < 128; off <<= 1) {
        int u = (t < 128 && t >= off) ? sh[t - off] : 0;
        __syncthreads();
        if (t < 128) sh[t] += u;
        __syncthreads();
    }
    int offset = (blockIdx.x == 0) ? 0 : sh[blockIdx.x - 1];
    int i = blockIdx.x * SCAN_BLK + t;
    int r = g_row[i] + offset;
    g_row[i] = r;
    g_fill[i] = r;
}

// ---------------- CSR fill ----------------
__global__ void fill_kernel(const int* __restrict__ ei, int E) {
    int i = blockIdx.x * blockDim.x + threadIdx.x;
    if (i < E / 2) {
        int2 s2 = ((const int2*)ei)[i];
        int2 d2 = ((const int2*)(ei + E))[i];
        int p0 = atomicAdd(&g_fill[d2.x], 1);
        g_csrc[p0] = s2.x;
        int p1 = atomicAdd(&g_fill[d2.y], 1);
        g_csrc[p1] = s2.y;
    }
}

// ---------------- mean aggregation (pull): one warp per dst node (proven R12) ----------------
__global__ void hop_kernel(const float* __restrict__ x, int pass, int n) {
    int w = (blockIdx.x * blockDim.x + threadIdx.x) >> 5;
    if (w >= n) return;
    int lane = threadIdx.x & 31;

    const float4* in = (pass == 0) ? (const float4*)x : (const float4*)g_hop1;
    float*        op = (pass == 0) ? g_hop1 : g_hop2;

    int beg = g_row[w];
    int end = g_row[w + 1];

    float ax = 0.f, ay = 0.f, az = 0.f, aw = 0.f;
    int j = beg;
    for (; j + 4 <= end; j += 4) {
        int s0 = __ldg(&g_csrc[j + 0]);
        int s1 = __ldg(&g_csrc[j + 1]);
        int s2 = __ldg(&g_csrc[j + 2]);
        int s3 = __ldg(&g_csrc[j + 3]);
        float4 v0 = __ldg(in + (size_t)s0 * 32 + lane);
        float4 v1 = __ldg(in + (size_t)s1 * 32 + lane);
        float4 v2 = __ldg(in + (size_t)s2 * 32 + lane);
        float4 v3 = __ldg(in + (size_t)s3 * 32 + lane);
        ax += v0.x; ay += v0.y; az += v0.z; aw += v0.w;
        ax += v1.x; ay += v1.y; az += v1.z; aw += v1.w;
        ax += v2.x; ay += v2.y; az += v2.z; aw += v2.w;
        ax += v3.x; ay += v3.y; az += v3.z; aw += v3.w;
    }
    for (; j < end; j++) {
        int s0 = __ldg(&g_csrc[j]);
        float4 v0 = __ldg(in + (size_t)s0 * 32 + lane);
        ax += v0.x; ay += v0.y; az += v0.z; aw += v0.w;
    }
    float inv = g_inv[w];
    float4 r = make_float4(ax * inv, ay * inv, az * inv, aw * inv);
    *((float4*)op + (size_t)w * 32 + lane) = r;
}

// ---------------- fp16 split helpers ----------------
// A: split into hi + lo fp16 (error ~2^-24).  B: fp16 hi only (error ~2^-12).
__device__ __forceinline__ void split2h(float f0, float f1, uint32_t& hi, uint32_t& lo) {
    __half h0 = __float2half_rn(f0);
    __half h1 = __float2half_rn(f1);
    __half l0 = __float2half_rn(f0 - __half2float(h0));
    __half l1 = __float2half_rn(f1 - __half2float(h1));
    __half2 hh = __halves2half2(h0, h1);
    __half2 ll = __halves2half2(l0, l1);
    hi = *(uint32_t*)&hh;
    lo = *(uint32_t*)&ll;
}
__device__ __forceinline__ uint32_t pack2h(float f0, float f1) {
    __half2 h = __floats2half2_rn(f0, f1);
    return *(uint32_t*)&h;
}

__device__ __forceinline__ void mma_f16(float* c, const uint32_t* a, const uint32_t* b) {
    asm volatile(
        "mma.sync.aligned.m16n8k16.row.col.f32.f16.f16.f32 "
        "{%0,%1,%2,%3}, {%4,%5,%6,%7}, {%8,%9}, {%0,%1,%2,%3};"
        : "+f"(c[0]), "+f"(c[1]), "+f"(c[2]), "+f"(c[3])
        : "r"(a[0]), "r"(a[1]), "r"(a[2]), "r"(a[3]), "r"(b[0]), "r"(b[1]));
}

// ---------------- HMMA split-fp16 fused concat-GEMM (2-pass) ----------------
// out = [x|hop1|hop2] @ W^T + b.  CTA: 128 nodes x 128 outs. 8 warps, warp 32x64.
// 2 passes per k-step: Ahi*Bh + Alo*Bh  (B fp16 rounding ~2^-12 dominates error).
#define SSTR 40   // padded fp16 row stride (conflict-free fragment LDS)
__global__ __launch_bounds__(256, 2)
void hmma_gemm_kernel(const float* __restrict__ x,
                      const float* __restrict__ W,     // [128, 384]
                      const float* __restrict__ bias,  // [128]
                      float* __restrict__ out, int n) {
    __shared__ __half Ahi[128][SSTR], Alo[128][SSTR];
    __shared__ __half Bh[128][SSTR];

    int tid = threadIdx.x;
    int wid = tid >> 5, lane = tid & 31;
    int wm = wid & 3;            // warp row:   m in [wm*32, +32)
    int wn = wid >> 2;           // warp col:   o in [wn*64, +64)
    int g = lane >> 2, tig = lane & 3;
    int m0 = blockIdx.x * 128;

    float acc[2][8][4];
#pragma unroll
    for (int mt = 0; mt < 2; mt++)
#pragma unroll
        for (int nt = 0; nt < 8; nt++)
#pragma unroll
            for (int q = 0; q < 4; q++) acc[mt][nt][q] = 0.f;

    int lrow = tid >> 1;                 // loader row 0..127
    int lh   = (tid & 1) * 16;           // k half within 32-chunk
    bool avalid = (m0 + lrow) < n;

#pragma unroll 1
    for (int kt = 0; kt < 12; kt++) {
        const float* A = (kt < 4) ? x : (kt < 8) ? g_hop1 : g_hop2;
        int ka = (kt & 3) * 32;

        float4 av[4], wv[4];
        const float4* ap = (const float4*)(A + (size_t)(m0 + lrow) * 128 + ka + lh);
        const float4* wp = (const float4*)(W + (size_t)lrow * 384 + kt * 32 + lh);
#pragma unroll
        for (int q = 0; q < 4; q++) {
            av[q] = avalid ? __ldg(ap + q) : make_float4(0.f, 0.f, 0.f, 0.f);
            wv[q] = __ldg(wp + q);
        }

        __syncthreads();   // previous tile fully consumed
#pragma unroll
        for (int q = 0; q < 4; q++) {
            uint32_t h0, l0, h1, l1;
            int kc = lh + q * 4;
            split2h(av[q].x, av[q].y, h0, l0);
            split2h(av[q].z, av[q].w, h1, l1);
            *(uint32_t*)&Ahi[lrow][kc]     = h0;
            *(uint32_t*)&Ahi[lrow][kc + 2] = h1;
            *(uint32_t*)&Alo[lrow][kc]     = l0;
            *(uint32_t*)&Alo[lrow][kc + 2] = l1;
            *(uint32_t*)&Bh[lrow][kc]      = pack2h(wv[q].x, wv[q].y);
            *(uint32_t*)&Bh[lrow][kc + 2]  = pack2h(wv[q].z, wv[q].w);
        }
        __syncthreads();

#pragma unroll
        for (int ks = 0; ks < 2; ks++) {
            int kb = ks * 16 + tig * 2;

            uint32_t bf[8][2];
#pragma unroll
            for (int nt = 0; nt < 8; nt++) {
                int nn = wn * 64 + nt * 8 + g;
                bf[nt][0] = *(const uint32_t*)&Bh[nn][kb];
                bf[nt][1] = *(const uint32_t*)&Bh[nn][kb + 8];
            }
#pragma unroll
            for (int mt = 0; mt < 2; mt++) {
                int am = wm * 32 + mt * 16 + g;
                uint32_t afh[4], afl[4];
                afh[0] = *(const uint32_t*)&Ahi[am][kb];
                afh[1] = *(const uint32_t*)&Ahi[am + 8][kb];
                afh[2] = *(const uint32_t*)&Ahi[am][kb + 8];
                afh[3] = *(const uint32_t*)&Ahi[am + 8][kb + 8];
                afl[0] = *(const uint32_t*)&Alo[am][kb];
                afl[1] = *(const uint32_t*)&Alo[am + 8][kb];
                afl[2] = *(const uint32_t*)&Alo[am][kb + 8];
                afl[3] = *(const uint32_t*)&Alo[am + 8][kb + 8];
#pragma unroll
                for (int nt = 0; nt < 8; nt++) {
                    mma_f16(acc[mt][nt], afh, bf[nt]);
                    mma_f16(acc[mt][nt], afl, bf[nt]);
                }
            }
        }
    }

    // epilogue: acc -> out (+bias)
#pragma unroll
    for (int mt = 0; mt < 2; mt++) {
        int row = m0 + wm * 32 + mt * 16 + g;
#pragma unroll
        for (int nt = 0; nt < 8; nt++) {
            int col = wn * 64 + nt * 8 + tig * 2;
            float2 bb = *(const float2*)&bias[col];
            if (row < n) {
                float2 r0 = make_float2(acc[mt][nt][0] + bb.x, acc[mt][nt][1] + bb.y);
                *(float2*)&out[(size_t)row * 128 + col] = r0;
            }
            if (row + 8 < n) {
                float2 r1 = make_float2(acc[mt][nt][2] + bb.x, acc[mt][nt][3] + bb.y);
                *(float2*)&out[(size_t)(row + 8) * 128 + col] = r1;
            }
        }
    }
}

// ---------------- launch (single stream) ----------------
extern "C" void kernel_launch(void* const* d_in, const int* in_sizes, int n_in,
                              void* d_out, int out_size) {
    const float* x    = (const float*)d_in[0];
    const int*   ei   = (const int*)d_in[1];      // int32 (JAX x64 disabled)
    const float* W    = (const float*)d_in[2];
    const float* bias = (const float*)d_in[3];
    float*       out  = (float*)d_out;

    int n = in_sizes[0] / D;      // 50000
    int E = in_sizes[1] / 2;      // 600000

    // CSR build (by destination)
    degree_kernel<<<(E / 2 + 255) / 256, 256>>>(ei, E);
    scan1_kernel<<<NSCAN, SCAN_BLK>>>();
    scan3_kernel<<<NSCAN, SCAN_BLK>>>();
    fill_kernel<<<(E / 2 + 255) / 256, 256>>>(ei, E);

    // two mean-propagation hops (fp32, proven)
    int hop_blocks = (n * 32 + 255) / 256;
    hop_kernel<<<hop_blocks, 256>>>(x, 0, n);
    hop_kernel<<<hop_blocks, 256>>>(x, 1, n);

    // split-fp16 HMMA GEMM, 2 accumulation passes
    hmma_gemm_kernel<<<(n + 127) / 128, 256>>>(x, W, bias, out, n);
}

// round 16
// speedup vs baseline: 1.3731x; 1.0699x over previous
#include <cuda_runtime.h>
#include <cuda_fp16.h>
#include <cstdint>

#define D 128
#define MAXN 50176        // padded node capacity (actual N = 50000)
#define MAXE 600000
#define SCAN_BLK 512
#define NSCAN (MAXN / SCAN_BLK)   // 98

// ---------------- scratch (no allocs allowed) ----------------
__device__ int   g_cnt[MAXN];          // zeroed in scan1 (self-restoring)
__device__ int   g_fill[MAXN];         // set by scan3 to row start each call
__device__ int   g_row[MAXN + 1];
__device__ int   g_bsum[NSCAN];
__device__ int   g_csrc[MAXE];
__device__ float g_inv[MAXN];
__device__ float g_hop1[MAXN * D];
__device__ float g_hop2[MAXN * D];

// ---------------- in-degree histogram (2 edges/thread) ----------------
__global__ void degree_kernel(const int* __restrict__ ei, int E) {
    int i = blockIdx.x * blockDim.x + threadIdx.x;
    if (i < E / 2) {
        int2 d2 = ((const int2*)(ei + E))[i];
        atomicAdd(&g_cnt[d2.x], 1);
        atomicAdd(&g_cnt[d2.y], 1);
    }
}

// ---------------- scan1: per-block exclusive prefix, block sum, inv-degree ----------------
__global__ void scan1_kernel() {
    __shared__ int sh[SCAN_BLK];
    int t = threadIdx.x;
    int i = blockIdx.x * SCAN_BLK + t;
    int v = g_cnt[i];
    g_cnt[i] = 0;                              // self-restore for next replay
    sh[t] = v;
    __syncthreads();
#pragma unroll
    for (int off = 1; off < SCAN_BLK; off <<= 1) {
        int u = (t >= off) ? sh[t - off] : 0;
        __syncthreads();
        sh[t] += u;
        __syncthreads();
    }
    g_row[i] = sh[t] - v;                      // exclusive within block
    g_inv[i] = 1.0f / fmaxf((float)v, 1.0f);
    if (t == SCAN_BLK - 1) g_bsum[blockIdx.x] = sh[t];
}

// ---------------- scan3: add block offsets (redundant per-block scan of bsum) ----------------
__global__ void scan3_kernel() {
    __shared__ int sh[128];
    int t = threadIdx.x;
    if (t < 128) sh[t] = (t < NSCAN) ? g_bsum[t] : 0;
    __syncthreads();
#pragma unroll
    for (int off = 1; off < 128; off <<= 1) {
        int u = (t < 128 && t >= off) ? sh[t - off] : 0;
        __syncthreads();
        if (t < 128) sh[t] += u;
        __syncthreads();
    }
    int offset = (blockIdx.x == 0) ? 0 : sh[blockIdx.x - 1];
    int i = blockIdx.x * SCAN_BLK + t;
    int r = g_row[i] + offset;
    g_row[i] = r;
    g_fill[i] = r;
}

// ---------------- CSR fill (4 edges/thread: deeper atomic pipelining) ----------------
__global__ void fill_kernel(const int* __restrict__ ei, int E) {
    int i = blockIdx.x * blockDim.x + threadIdx.x;
    if (i < E / 4) {
        int4 s4 = ((const int4*)ei)[i];
        int4 d4 = ((const int4*)(ei + E))[i];
        int p0 = atomicAdd(&g_fill[d4.x], 1);
        int p1 = atomicAdd(&g_fill[d4.y], 1);
        int p2 = atomicAdd(&g_fill[d4.z], 1);
        int p3 = atomicAdd(&g_fill[d4.w], 1);
        g_csrc[p0] = s4.x;
        g_csrc[p1] = s4.y;
        g_csrc[p2] = s4.z;
        g_csrc[p3] = s4.w;
    }
}

// ---------------- mean aggregation (pull): one warp per dst node (proven R12) ----------------
__global__ void hop_kernel(const float* __restrict__ x, int pass, int n) {
    int w = (blockIdx.x * blockDim.x + threadIdx.x) >> 5;
    if (w >= n) return;
    int lane = threadIdx.x & 31;

    const float4* in = (pass == 0) ? (const float4*)x : (const float4*)g_hop1;
    float*        op = (pass == 0) ? g_hop1 : g_hop2;

    int beg = g_row[w];
    int end = g_row[w + 1];

    float ax = 0.f, ay = 0.f, az = 0.f, aw = 0.f;
    int j = beg;
    for (; j + 4 <= end; j += 4) {
        int s0 = __ldg(&g_csrc[j + 0]);
        int s1 = __ldg(&g_csrc[j + 1]);
        int s2 = __ldg(&g_csrc[j + 2]);
        int s3 = __ldg(&g_csrc[j + 3]);
        float4 v0 = __ldg(in + (size_t)s0 * 32 + lane);
        float4 v1 = __ldg(in + (size_t)s1 * 32 + lane);
        float4 v2 = __ldg(in + (size_t)s2 * 32 + lane);
        float4 v3 = __ldg(in + (size_t)s3 * 32 + lane);
        ax += v0.x; ay += v0.y; az += v0.z; aw += v0.w;
        ax += v1.x; ay += v1.y; az += v1.z; aw += v1.w;
        ax += v2.x; ay += v2.y; az += v2.z; aw += v2.w;
        ax += v3.x; ay += v3.y; az += v3.z; aw += v3.w;
    }
    for (; j < end; j++) {
        int s0 = __ldg(&g_csrc[j]);
        float4 v0 = __ldg(in + (size_t)s0 * 32 + lane);
        ax += v0.x; ay += v0.y; az += v0.z; aw += v0.w;
    }
    float inv = g_inv[w];
    float4 r = make_float4(ax * inv, ay * inv, az * inv, aw * inv);
    *((float4*)op + (size_t)w * 32 + lane) = r;
}

// ---------------- fp16 helpers ----------------
__device__ __forceinline__ uint32_t pack2h(float f0, float f1) {
    __half2 h = __floats2half2_rn(f0, f1);
    return *(uint32_t*)&h;
}

__device__ __forceinline__ void mma_f16(float* c, const uint32_t* a, const uint32_t* b) {
    asm volatile(
        "mma.sync.aligned.m16n8k16.row.col.f32.f16.f16.f32 "
        "{%0,%1,%2,%3}, {%4,%5,%6,%7}, {%8,%9}, {%0,%1,%2,%3};"
        : "+f"(c[0]), "+f"(c[1]), "+f"(c[2]), "+f"(c[3])
        : "r"(a[0]), "r"(a[1]), "r"(a[2]), "r"(a[3]), "r"(b[0]), "r"(b[1]));
}

// ---------------- HMMA fp16 fused concat-GEMM (single pass) ----------------
// out = [x|hop1|hop2] @ W^T + b.  CTA: 128 nodes x 128 outs. 8 warps, warp 32x64.
// A and B both fp16-rounded; error ~2^-12 each, combined ~3-4e-4 rel.
#define SSTR 40   // padded fp16 row stride (conflict-free fragment LDS)
__global__ __launch_bounds__(256, 2)
void hmma_gemm_kernel(const float* __restrict__ x,
                      const float* __restrict__ W,     // [128, 384]
                      const float* __restrict__ bias,  // [128]
                      float* __restrict__ out, int n) {
    __shared__ __half Ah[128][SSTR];
    __shared__ __half Bh[128][SSTR];

    int tid = threadIdx.x;
    int wid = tid >> 5, lane = tid & 31;
    int wm = wid & 3;            // warp row:   m in [wm*32, +32)
    int wn = wid >> 2;           // warp col:   o in [wn*64, +64)
    int g = lane >> 2, tig = lane & 3;
    int m0 = blockIdx.x * 128;

    float acc[2][8][4];
#pragma unroll
    for (int mt = 0; mt < 2; mt++)
#pragma unroll
        for (int nt = 0; nt < 8; nt++)
#pragma unroll
            for (int q = 0; q < 4; q++) acc[mt][nt][q] = 0.f;

    int lrow = tid >> 1;                 // loader row 0..127
    int lh   = (tid & 1) * 16;           // k half within 32-chunk
    bool avalid = (m0 + lrow) < n;

#pragma unroll 1
    for (int kt = 0; kt < 12; kt++) {
        const float* A = (kt < 4) ? x : (kt < 8) ? g_hop1 : g_hop2;
        int ka = (kt & 3) * 32;

        float4 av[4], wv[4];
        const float4* ap = (const float4*)(A + (size_t)(m0 + lrow) * 128 + ka + lh);
        const float4* wp = (const float4*)(W + (size_t)lrow * 384 + kt * 32 + lh);
#pragma unroll
        for (int q = 0; q < 4; q++) {
            av[q] = avalid ? __ldg(ap + q) : make_float4(0.f, 0.f, 0.f, 0.f);
            wv[q] = __ldg(wp + q);
        }

        __syncthreads();   // previous tile fully consumed
#pragma unroll
        for (int q = 0; q < 4; q++) {
            int kc = lh + q * 4;
            *(uint32_t*)&Ah[lrow][kc]     = pack2h(av[q].x, av[q].y);
            *(uint32_t*)&Ah[lrow][kc + 2] = pack2h(av[q].z, av[q].w);
            *(uint32_t*)&Bh[lrow][kc]     = pack2h(wv[q].x, wv[q].y);
            *(uint32_t*)&Bh[lrow][kc + 2] = pack2h(wv[q].z, wv[q].w);
        }
        __syncthreads();

#pragma unroll
        for (int ks = 0; ks < 2; ks++) {
            int kb = ks * 16 + tig * 2;

            uint32_t bf[8][2];
#pragma unroll
            for (int nt = 0; nt < 8; nt++) {
                int nn = wn * 64 + nt * 8 + g;
                bf[nt][0] = *(const uint32_t*)&Bh[nn][kb];
                bf[nt][1] = *(const uint32_t*)&Bh[nn][kb + 8];
            }
#pragma unroll
            for (int mt = 0; mt < 2; mt++) {
                int am = wm * 32 + mt * 16 + g;
                uint32_t af[4];
                af[0] = *(const uint32_t*)&Ah[am][kb];
                af[1] = *(const uint32_t*)&Ah[am + 8][kb];
                af[2] = *(const uint32_t*)&Ah[am][kb + 8];
                af[3] = *(const uint32_t*)&Ah[am + 8][kb + 8];
#pragma unroll
                for (int nt = 0; nt < 8; nt++)
                    mma_f16(acc[mt][nt], af, bf[nt]);
            }
        }
    }

    // epilogue: acc -> out (+bias)
#pragma unroll
    for (int mt = 0; mt < 2; mt++) {
        int row = m0 + wm * 32 + mt * 16 + g;
#pragma unroll
        for (int nt = 0; nt < 8; nt++) {
            int col = wn * 64 + nt * 8 + tig * 2;
            float2 bb = *(const float2*)&bias[col];
            if (row < n) {
                float2 r0 = make_float2(acc[mt][nt][0] + bb.x, acc[mt][nt][1] + bb.y);
                *(float2*)&out[(size_t)row * 128 + col] = r0;
            }
            if (row + 8 < n) {
                float2 r1 = make_float2(acc[mt][nt][2] + bb.x, acc[mt][nt][3] + bb.y);
                *(float2*)&out[(size_t)(row + 8) * 128 + col] = r1;
            }
        }
    }
}

// ---------------- launch (single stream) ----------------
extern "C" void kernel_launch(void* const* d_in, const int* in_sizes, int n_in,
                              void* d_out, int out_size) {
    const float* x    = (const float*)d_in[0];
    const int*   ei   = (const int*)d_in[1];      // int32 (JAX x64 disabled)
    const float* W    = (const float*)d_in[2];
    const float* bias = (const float*)d_in[3];
    float*       out  = (float*)d_out;

    int n = in_sizes[0] / D;      // 50000
    int E = in_sizes[1] / 2;      // 600000

    // CSR build (by destination)
    degree_kernel<<<(E / 2 + 255) / 256, 256>>>(ei, E);
    scan1_kernel<<<NSCAN, SCAN_BLK>>>();
    scan3_kernel<<<NSCAN, SCAN_BLK>>>();
    fill_kernel<<<(E / 4 + 255) / 256, 256>>>(ei, E);

    // two mean-propagation hops (fp32, proven)
    int hop_blocks = (n * 32 + 255) / 256;
    hop_kernel<<<hop_blocks, 256>>>(x, 0, n);
    hop_kernel<<<hop_blocks, 256>>>(x, 1, n);

    // fp16 HMMA GEMM, single accumulation pass
    hmma_gemm_kernel<<<(n + 127) / 128, 256>>>(x, W, bias, out, n);
}